// round 4
// baseline (speedup 1.0000x reference)
#include <cuda_runtime.h>
#include <math.h>

#define C 150
#define D 128
#define NCHUNK 18
#define NSLICE 8
#define GRID1 (NSLICE * NCHUNK)   // 144 CTAs = one clean wave on 148 SMs
#define COLS 16                   // columns per CTA slice
#define NB0 304                   // K0 blocks
#define SKIPC 0xFFFFu
#define NMAX 2097152
#define WACC_F (2*C*COLS)         // 4800 floats per-warp accumulator
#define INV_TEMP 5.0f

// ---- device scratch (fully re-written every launch) ----
__device__ unsigned short g_codes[NMAX];            // bucket code per point (or SKIPC)
__device__ int            g_cntpart[NB0 * 2 * C];   // per-K0-block integer histograms
__device__ float          g_part1[GRID1 * WACC_F];  // per-CTA partial sums
__device__ float          g_ab[2 * C * D];          // normalized means (A then B)
__device__ float          g_contrib[C];             // per-class symmetric-NCE contribution

// ---------------------------------------------------------------------------
// K0: encode metadata -> u16 codes (read 24MB once) + deterministic int counts.
// ---------------------------------------------------------------------------
__global__ __launch_bounds__(256)
void k0_encode(const int* __restrict__ mask, const int* __restrict__ seg,
               const int* __restrict__ grp, int N, int NPAD)
{
    __shared__ int hist[2 * C];
    for (int i = threadIdx.x; i < 2 * C; i += 256) hist[i] = 0;
    __syncthreads();

    const int pairs = NPAD >> 1;
    for (int p = blockIdx.x * 256 + threadIdx.x; p < pairs; p += NB0 * 256) {
        const int i0 = 2 * p;
        unsigned c0 = SKIPC, c1 = SKIPC;
        if (i0 + 1 < N) {
            int2 m = *(const int2*)(mask + i0);
            int2 s = *(const int2*)(seg  + i0);
            int2 g = *(const int2*)(grp  + i0);
            if (m.x > 0 && s.x != -1 && (unsigned)g.x <= 1u)
                c0 = (unsigned)g.x * C + (unsigned)min(max(s.x, 0), C - 1);
            if (m.y > 0 && s.y != -1 && (unsigned)g.y <= 1u)
                c1 = (unsigned)g.y * C + (unsigned)min(max(s.y, 0), C - 1);
        } else if (i0 < N) {
            int m = mask[i0], s = seg[i0], g = grp[i0];
            if (m > 0 && s != -1 && (unsigned)g <= 1u)
                c0 = (unsigned)g * C + (unsigned)min(max(s, 0), C - 1);
        }
        if (c0 < 2 * C) atomicAdd(&hist[c0], 1);
        if (c1 < 2 * C) atomicAdd(&hist[c1], 1);
        ((unsigned*)g_codes)[p] = c0 | (c1 << 16);
    }
    __syncthreads();
    for (int i = threadIdx.x; i < 2 * C; i += 256)
        g_cntpart[blockIdx.x * 2 * C + i] = hist[i];
}

// ---------------------------------------------------------------------------
// K1: column-sliced segmented sums (R2 structure). Half-warp 0 handles even
// points, half-warp 1 odd points of each pair; when a pair shares a bucket
// (warp-uniform, ~0.33%) the halves are combined via shfl_xor and half 0
// writes — race-free and deterministic with near-zero overhead.
// ---------------------------------------------------------------------------
__global__ __launch_bounds__(256, 1)
void k1_accumulate(const float* __restrict__ pred, int N, int chTiles)
{
    extern __shared__ float sm[];
    const int tid  = threadIdx.x;
    const int wid  = tid >> 5;
    const int lane = tid & 31;
    const int half = lane >> 4;       // 0: even point of pair, 1: odd point
    const int cj   = lane & 15;       // column within slice
    float* wacc = sm + wid * WACC_F;

    for (int i = tid; i < 8 * WACC_F; i += 256) sm[i] = 0.0f;
    __syncthreads();

    const int slice   = blockIdx.x / NCHUNK;
    const int chunk   = blockIdx.x % NCHUNK;
    const int colbase = slice * COLS;
    const unsigned* codes32 = (const unsigned*)g_codes;

    auto loadtile = [&](int tt, float* v, unsigned& pk) {
        const int base = (chunk * chTiles + tt) * 64;
        pk = codes32[(base >> 1) + lane];
        if (base + 64 <= N) {
            const float* p = pred + (size_t)(base + half) * D + colbase + cj;
            #pragma unroll
            for (int u = 0; u < 32; u++) v[u] = p[(size_t)u * (2 * D)];
        } else {
            #pragma unroll
            for (int u = 0; u < 32; u++) {
                int idx = base + 2 * u + half;
                idx = idx < N ? idx : N - 1;          // clamp; code is SKIPC for OOB
                v[u] = pred[(size_t)idx * D + colbase + cj];
            }
        }
    };

    auto accum = [&](const float* v, unsigned pk) {
        #pragma unroll
        for (int u = 0; u < 32; u++) {
            const unsigned pp = __shfl_sync(0xffffffffu, pk, u);
            const unsigned lo = pp & 0xffffu;
            const unsigned hi = pp >> 16;
            if (lo == hi) {                       // warp-uniform rare branch
                if (lo < 2u * C) {
                    const float vv = v[u] + __shfl_xor_sync(0xffffffffu, v[u], 16);
                    if (half == 0) wacc[lo * COLS + cj] += vv;
                }
            } else {
                const unsigned bc = half ? hi : lo;
                if (bc < 2u * C) wacc[bc * COLS + cj] += v[u];
            }
        }
    };

    float va[32], vb[32];
    unsigned pka, pkb;
    int t = wid;
    if (t < chTiles) {
        loadtile(t, va, pka);
        while (true) {
            int tn = t + 8;
            if (tn < chTiles) {
                loadtile(tn, vb, pkb);
                accum(va, pka);
                int tnn = tn + 8;
                if (tnn < chTiles) {
                    loadtile(tnn, va, pka);
                    accum(vb, pkb);
                    t = tnn;
                } else { accum(vb, pkb); break; }
            } else { accum(va, pka); break; }
        }
    }
    __syncthreads();

    // reduce 8 warp slabs -> one CTA partial slab (deterministic order)
    for (int i = tid; i < WACC_F; i += 256) {
        float s = 0.0f;
        #pragma unroll
        for (int w = 0; w < 8; w++) s += sm[w * WACC_F + i];
        g_part1[(size_t)blockIdx.x * WACC_F + i] = s;
    }
}

// ---------------------------------------------------------------------------
// K2: reduce partials -> mean -> L2 normalize. grid = 2*C blocks, 128 threads.
// ---------------------------------------------------------------------------
__global__ void k2_mean_norm()
{
    __shared__ float red[D];
    const int gc = blockIdx.x;     // g*C + c
    const int d  = threadIdx.x;    // column 0..127

    float pc = 0.0f;
    for (int b = d; b < NB0; b += D) pc += (float)g_cntpart[b * 2 * C + gc];
    red[d] = pc; __syncthreads();
    for (int s = 64; s > 0; s >>= 1) { if (d < s) red[d] += red[d + s]; __syncthreads(); }
    const float cnt = fmaxf(red[0], 1.0f);
    __syncthreads();

    const int cs = d >> 4, j = d & 15;   // slice, col-in-slice (col == d)
    float s = 0.0f;
    #pragma unroll
    for (int h = 0; h < NCHUNK; h++)
        s += g_part1[(size_t)(cs * NCHUNK + h) * WACC_F + gc * COLS + j];
    const float mean = s / cnt;

    red[d] = mean * mean; __syncthreads();
    for (int s2 = 64; s2 > 0; s2 >>= 1) { if (d < s2) red[d] += red[d + s2]; __syncthreads(); }
    const float inv = rsqrtf(red[0]);

    g_ab[gc * D + d] = mean * inv;
}

// ---------------------------------------------------------------------------
// K3: block i computes logits row i AND column i in parallel groups of 256
// threads each, then both logsumexps. grid = C blocks, 512 threads.
// ---------------------------------------------------------------------------
__global__ __launch_bounds__(512)
void k3_lse()
{
    extern __shared__ float s3[];
    float* aT  = s3;                 // [D][152]
    float* bT  = aT + D * 152;       // [D][152]
    float* ai  = bT + D * 152;       // [D]
    float* bi  = ai + D;             // [D]
    float* red = bi + D;             // [2][256]
    __shared__ float diag_s, lse_s[2];

    const int i = blockIdx.x, tid = threadIdx.x;
    const int g2 = tid >> 8;         // 0: row group, 1: col group
    const int j  = tid & 255;

    for (int idx = tid; idx < C * D; idx += 512) {
        const int c = idx >> 7, d = idx & 127;
        aT[d * 152 + c] = g_ab[idx];
        bT[d * 152 + c] = g_ab[C * D + idx];
    }
    if (tid < D)            ai[tid] = g_ab[i * D + tid];
    else if (tid < 2 * D)   bi[tid - D] = g_ab[C * D + i * D + (tid - D)];
    __syncthreads();

    float x = -1e30f;
    if (j < C) {
        const float* vec = g2 ? bi : ai;
        const float* mat = g2 ? aT : bT;
        float xs = 0.0f;
        #pragma unroll 8
        for (int k = 0; k < D; k++) xs += vec[k] * mat[k * 152 + j];
        x = xs * INV_TEMP;
        if (g2 == 0 && j == i) diag_s = x;
    }

    // parallel logsumexp per group (both groups run the same barriers)
    red[tid] = x; __syncthreads();
    for (int s = 128; s > 0; s >>= 1) {
        if (j < s) red[tid] = fmaxf(red[tid], red[tid + s]);
        __syncthreads();
    }
    const float mx = red[g2 << 8]; __syncthreads();
    red[tid] = (j < C) ? expf(x - mx) : 0.0f; __syncthreads();
    for (int s = 128; s > 0; s >>= 1) {
        if (j < s) red[tid] += red[tid + s];
        __syncthreads();
    }
    if (j == 0) lse_s[g2] = mx + logf(red[g2 << 8]);
    __syncthreads();

    if (tid == 0) g_contrib[i] = lse_s[0] + lse_s[1] - 2.0f * diag_s;
}

// ---------------------------------------------------------------------------
// K4: final scalar. 1 block, 256 threads.
// ---------------------------------------------------------------------------
__global__ void k4_final(float* __restrict__ out)
{
    __shared__ float red[256];
    const int tid = threadIdx.x;
    red[tid] = (tid < C) ? g_contrib[tid] : 0.0f; __syncthreads();
    for (int s = 128; s > 0; s >>= 1) { if (tid < s) red[tid] += red[tid + s]; __syncthreads(); }
    if (tid == 0) out[0] = red[0] * (1.0f / (2.0f * C));
}

// ---------------------------------------------------------------------------
extern "C" void kernel_launch(void* const* d_in, const int* in_sizes, int n_in,
                              void* d_out, int out_size)
{
    const float* pred = (const float*)d_in[0];
    // d_in[1] = target (unused by the loss math)
    const int* mask = (const int*)d_in[2];
    const int* seg  = (const int*)d_in[3];
    const int* grp  = (const int*)d_in[4];
    const int N = in_sizes[2];

    const int totTiles = (N + 63) / 64;
    const int chTiles  = (totTiles + NCHUNK - 1) / NCHUNK;
    const int NPAD     = NCHUNK * chTiles * 64;   // <= NMAX for N <= ~2.09M

    const size_t smem1 = 8 * WACC_F * sizeof(float);               // 153.6 KB
    cudaFuncSetAttribute(k1_accumulate, cudaFuncAttributeMaxDynamicSharedMemorySize, (int)smem1);
    const size_t smem3 = (2 * D * 152 + 2 * D + 512) * sizeof(float);
    cudaFuncSetAttribute(k3_lse, cudaFuncAttributeMaxDynamicSharedMemorySize, (int)smem3);

    k0_encode<<<NB0, 256>>>(mask, seg, grp, N, NPAD);
    k1_accumulate<<<GRID1, 256, smem1>>>(pred, N, chTiles);
    k2_mean_norm<<<2 * C, D>>>();
    k3_lse<<<C, 512, smem3>>>();
    k4_final<<<1, 256>>>((float*)d_out);
}

// round 5
// speedup vs baseline: 1.4137x; 1.4137x over previous
#include <cuda_runtime.h>
#include <math.h>

#define C 150
#define D 128
#define NCHUNK 18
#define NSLICE 8
#define GRID1 (NSLICE * NCHUNK)   // 144 CTAs = one clean wave on 148 SMs
#define COLS 16                   // columns per CTA slice
#define NB0 304                   // K0 blocks
#define SKIPC 0xFFFFu
#define NMAX 2097152
#define WACC_F (2*C*COLS)         // 4800 floats per half-warp accumulator slab
#define NSLAB 8                   // 4 warps x 2 half-warps
#define INV_TEMP 5.0f

// ---- device scratch (fully re-written every launch) ----
__device__ unsigned short g_codes[NMAX];            // bucket code per point (or SKIPC)
__device__ int            g_cntpart[NB0 * 2 * C];   // per-K0-block integer histograms
__device__ float          g_part1[GRID1 * WACC_F];  // per-CTA partial sums
__device__ float          g_ab[2 * C * D];          // normalized means (A then B)
__device__ float          g_contrib[C];             // per-class symmetric-NCE contribution

// ---------------------------------------------------------------------------
// K0: encode metadata -> u16 codes (read 24MB once) + deterministic int counts.
// ---------------------------------------------------------------------------
__global__ __launch_bounds__(256)
void k0_encode(const int* __restrict__ mask, const int* __restrict__ seg,
               const int* __restrict__ grp, int N, int NPAD)
{
    __shared__ int hist[2 * C];
    for (int i = threadIdx.x; i < 2 * C; i += 256) hist[i] = 0;
    __syncthreads();

    const int pairs = NPAD >> 1;
    for (int p = blockIdx.x * 256 + threadIdx.x; p < pairs; p += NB0 * 256) {
        const int i0 = 2 * p;
        unsigned c0 = SKIPC, c1 = SKIPC;
        if (i0 + 1 < N) {
            int2 m = *(const int2*)(mask + i0);
            int2 s = *(const int2*)(seg  + i0);
            int2 g = *(const int2*)(grp  + i0);
            if (m.x > 0 && s.x != -1 && (unsigned)g.x <= 1u)
                c0 = (unsigned)g.x * C + (unsigned)min(max(s.x, 0), C - 1);
            if (m.y > 0 && s.y != -1 && (unsigned)g.y <= 1u)
                c1 = (unsigned)g.y * C + (unsigned)min(max(s.y, 0), C - 1);
        } else if (i0 < N) {
            int m = mask[i0], s = seg[i0], g = grp[i0];
            if (m > 0 && s != -1 && (unsigned)g <= 1u)
                c0 = (unsigned)g * C + (unsigned)min(max(s, 0), C - 1);
        }
        if (c0 < 2 * C) atomicAdd(&hist[c0], 1);
        if (c1 < 2 * C) atomicAdd(&hist[c1], 1);
        ((unsigned*)g_codes)[p] = c0 | (c1 << 16);
    }
    __syncthreads();
    for (int i = threadIdx.x; i < 2 * C; i += 256)
        g_cntpart[blockIdx.x * 2 * C + i] = hist[i];
}

// ---------------------------------------------------------------------------
// K1: column-sliced segmented sums. 128 threads / 4 warps; each HALF-WARP has
// a private accumulator slab, so the two points of a pair can never collide
// (race-free, deterministic) with the exact R2 instruction mix: shfl broadcast
// of codes + predicated SMEM RMW, zero branches in the hot loop.
// 3-stage software pipeline keeps ~55 LDG in flight per warp.
// ---------------------------------------------------------------------------
__global__ __launch_bounds__(128, 1)
void k1_accumulate(const float* __restrict__ pred, int N, int chTiles)
{
    extern __shared__ float sm[];
    const int tid  = threadIdx.x;
    const int wid  = tid >> 5;
    const int lane = tid & 31;
    const int half = lane >> 4;       // 0: even point of pair, 1: odd point
    const int cj   = lane & 15;       // column within slice
    float* wacc = sm + (wid * 2 + half) * WACC_F;   // private per half-warp

    for (int i = tid; i < NSLAB * WACC_F; i += 128) sm[i] = 0.0f;
    __syncthreads();

    const int slice   = blockIdx.x / NCHUNK;
    const int chunk   = blockIdx.x % NCHUNK;
    const int colbase = slice * COLS;
    const unsigned* codes32 = (const unsigned*)g_codes;

    auto loadtile = [&](int tt, float* v, unsigned& pk) {
        const int base = (chunk * chTiles + tt) * 64;
        pk = codes32[(base >> 1) + lane];
        if (base + 64 <= N) {
            const float* p = pred + (size_t)(base + half) * D + colbase + cj;
            #pragma unroll
            for (int u = 0; u < 32; u++) v[u] = p[(size_t)u * (2 * D)];
        } else {
            #pragma unroll
            for (int u = 0; u < 32; u++) {
                int idx = base + 2 * u + half;
                idx = idx < N ? idx : N - 1;          // clamp; code is SKIPC for OOB
                v[u] = pred[(size_t)idx * D + colbase + cj];
            }
        }
    };

    auto accum = [&](const float* v, unsigned pk) {
        #pragma unroll
        for (int u = 0; u < 32; u++) {
            const unsigned pp = __shfl_sync(0xffffffffu, pk, u);
            const unsigned bc = half ? (pp >> 16) : (pp & 0xffffu);
            if (bc < 2u * C) wacc[bc * COLS + cj] += v[u];   // predicated RMW
        }
    };

    // tiles for this warp: wid, wid+4, wid+8, ...
    const int nT = (chTiles > wid) ? ((chTiles - wid + 3) >> 2) : 0;

    float va[32], vb[32], vc[32];
    unsigned pka, pkb, pkc;
    if (nT >= 1) loadtile(wid,      va, pka);
    if (nT >= 2) loadtile(wid + 4,  vb, pkb);
    if (nT >= 3) loadtile(wid + 8,  vc, pkc);

    int i = 0;
    for (;;) {
        if (i >= nT) break;
        accum(va, pka);
        if (i + 3 < nT) loadtile(wid + 4 * (i + 3), va, pka);
        i++;
        if (i >= nT) break;
        accum(vb, pkb);
        if (i + 3 < nT) loadtile(wid + 4 * (i + 3), vb, pkb);
        i++;
        if (i >= nT) break;
        accum(vc, pkc);
        if (i + 3 < nT) loadtile(wid + 4 * (i + 3), vc, pkc);
        i++;
    }
    __syncthreads();

    // reduce 8 half-warp slabs -> one CTA partial slab (deterministic order)
    for (int k = tid; k < WACC_F; k += 128) {
        float s = 0.0f;
        #pragma unroll
        for (int w = 0; w < NSLAB; w++) s += sm[w * WACC_F + k];
        g_part1[(size_t)blockIdx.x * WACC_F + k] = s;
    }
}

// ---------------------------------------------------------------------------
// K2: reduce partials -> mean -> L2 normalize. grid = 2*C blocks, 128 threads.
// ---------------------------------------------------------------------------
__global__ void k2_mean_norm()
{
    __shared__ float red[D];
    const int gc = blockIdx.x;     // g*C + c
    const int d  = threadIdx.x;    // column 0..127

    float pc = 0.0f;
    for (int b = d; b < NB0; b += D) pc += (float)g_cntpart[b * 2 * C + gc];
    red[d] = pc; __syncthreads();
    for (int s = 64; s > 0; s >>= 1) { if (d < s) red[d] += red[d + s]; __syncthreads(); }
    const float cnt = fmaxf(red[0], 1.0f);
    __syncthreads();

    const int cs = d >> 4, j = d & 15;   // slice, col-in-slice (col == d)
    float s = 0.0f;
    #pragma unroll
    for (int h = 0; h < NCHUNK; h++)
        s += g_part1[(size_t)(cs * NCHUNK + h) * WACC_F + gc * COLS + j];
    const float mean = s / cnt;

    red[d] = mean * mean; __syncthreads();
    for (int s2 = 64; s2 > 0; s2 >>= 1) { if (d < s2) red[d] += red[d + s2]; __syncthreads(); }
    const float inv = rsqrtf(red[0]);

    g_ab[gc * D + d] = mean * inv;
}

// ---------------------------------------------------------------------------
// K3: block i computes logits row i AND column i in parallel groups of 256
// threads each, then both logsumexps. grid = C blocks, 512 threads.
// ---------------------------------------------------------------------------
__global__ __launch_bounds__(512)
void k3_lse()
{
    extern __shared__ float s3[];
    float* aT  = s3;                 // [D][152]
    float* bT  = aT + D * 152;       // [D][152]
    float* ai  = bT + D * 152;       // [D]
    float* bi  = ai + D;             // [D]
    float* red = bi + D;             // [2][256]
    __shared__ float diag_s, lse_s[2];

    const int i = blockIdx.x, tid = threadIdx.x;
    const int g2 = tid >> 8;         // 0: row group, 1: col group
    const int j  = tid & 255;

    for (int idx = tid; idx < C * D; idx += 512) {
        const int c = idx >> 7, d = idx & 127;
        aT[d * 152 + c] = g_ab[idx];
        bT[d * 152 + c] = g_ab[C * D + idx];
    }
    if (tid < D)            ai[tid] = g_ab[i * D + tid];
    else if (tid < 2 * D)   bi[tid - D] = g_ab[C * D + i * D + (tid - D)];
    __syncthreads();

    float x = -1e30f;
    if (j < C) {
        const float* vec = g2 ? bi : ai;
        const float* mat = g2 ? aT : bT;
        float xs = 0.0f;
        #pragma unroll 8
        for (int k = 0; k < D; k++) xs += vec[k] * mat[k * 152 + j];
        x = xs * INV_TEMP;
        if (g2 == 0 && j == i) diag_s = x;
    }

    // parallel logsumexp per group (both groups run the same barriers)
    red[tid] = x; __syncthreads();
    for (int s = 128; s > 0; s >>= 1) {
        if (j < s) red[tid] = fmaxf(red[tid], red[tid + s]);
        __syncthreads();
    }
    const float mx = red[g2 << 8]; __syncthreads();
    red[tid] = (j < C) ? expf(x - mx) : 0.0f; __syncthreads();
    for (int s = 128; s > 0; s >>= 1) {
        if (j < s) red[tid] += red[tid + s];
        __syncthreads();
    }
    if (j == 0) lse_s[g2] = mx + logf(red[g2 << 8]);
    __syncthreads();

    if (tid == 0) g_contrib[i] = lse_s[0] + lse_s[1] - 2.0f * diag_s;
}

// ---------------------------------------------------------------------------
// K4: final scalar. 1 block, 256 threads.
// ---------------------------------------------------------------------------
__global__ void k4_final(float* __restrict__ out)
{
    __shared__ float red[256];
    const int tid = threadIdx.x;
    red[tid] = (tid < C) ? g_contrib[tid] : 0.0f; __syncthreads();
    for (int s = 128; s > 0; s >>= 1) { if (tid < s) red[tid] += red[tid + s]; __syncthreads(); }
    if (tid == 0) out[0] = red[0] * (1.0f / (2.0f * C));
}

// ---------------------------------------------------------------------------
extern "C" void kernel_launch(void* const* d_in, const int* in_sizes, int n_in,
                              void* d_out, int out_size)
{
    const float* pred = (const float*)d_in[0];
    // d_in[1] = target (unused by the loss math)
    const int* mask = (const int*)d_in[2];
    const int* seg  = (const int*)d_in[3];
    const int* grp  = (const int*)d_in[4];
    const int N = in_sizes[2];

    const int totTiles = (N + 63) / 64;
    const int chTiles  = (totTiles + NCHUNK - 1) / NCHUNK;
    const int NPAD     = NCHUNK * chTiles * 64;   // <= NMAX for N <= ~2.09M

    const size_t smem1 = NSLAB * WACC_F * sizeof(float);            // 153.6 KB
    cudaFuncSetAttribute(k1_accumulate, cudaFuncAttributeMaxDynamicSharedMemorySize, (int)smem1);
    const size_t smem3 = (2 * D * 152 + 2 * D + 512) * sizeof(float);
    cudaFuncSetAttribute(k3_lse, cudaFuncAttributeMaxDynamicSharedMemorySize, (int)smem3);

    k0_encode<<<NB0, 256>>>(mask, seg, grp, N, NPAD);
    k1_accumulate<<<GRID1, 128, smem1>>>(pred, N, chTiles);
    k2_mean_norm<<<2 * C, D>>>();
    k3_lse<<<C, 512, smem3>>>();
    k4_final<<<1, 256>>>((float*)d_out);
}

// round 6
// speedup vs baseline: 1.8812x; 1.3307x over previous
#include <cuda_runtime.h>
#include <math.h>

#define C 150
#define D 128
#define NCHUNK 18
#define NSLICE 8
#define GRID1 (NSLICE * NCHUNK)   // 144 CTAs = one clean wave on 148 SMs
#define COLS 16                   // columns per CTA slice
#define NB0 304                   // K0 blocks
#define SKIPC 0xFFFFu
#define NMAX 2097152
#define WACC_F (2*C*COLS)         // 4800 floats per-warp accumulator
#define INV_TEMP 5.0f

// ---- device scratch (fully re-written every launch) ----
__device__ unsigned short g_codes[NMAX];            // bucket code per point (or SKIPC)
__device__ int            g_cntpart[NB0 * 2 * C];   // per-K0-block integer histograms
__device__ float          g_part1[GRID1 * WACC_F];  // per-CTA partial sums
__device__ float          g_ab[2 * C * D];          // normalized means (A then B)
__device__ float          g_contrib[C];             // per-class symmetric-NCE contribution

// ---------------------------------------------------------------------------
// K0: encode metadata -> u16 codes (read 24MB once) + deterministic int counts.
// ---------------------------------------------------------------------------
__global__ __launch_bounds__(256)
void k0_encode(const int* __restrict__ mask, const int* __restrict__ seg,
               const int* __restrict__ grp, int N, int NPAD)
{
    __shared__ int hist[2 * C];
    for (int i = threadIdx.x; i < 2 * C; i += 256) hist[i] = 0;
    __syncthreads();

    const int pairs = NPAD >> 1;
    for (int p = blockIdx.x * 256 + threadIdx.x; p < pairs; p += NB0 * 256) {
        const int i0 = 2 * p;
        unsigned c0 = SKIPC, c1 = SKIPC;
        if (i0 + 1 < N) {
            int2 m = *(const int2*)(mask + i0);
            int2 s = *(const int2*)(seg  + i0);
            int2 g = *(const int2*)(grp  + i0);
            if (m.x > 0 && s.x != -1 && (unsigned)g.x <= 1u)
                c0 = (unsigned)g.x * C + (unsigned)min(max(s.x, 0), C - 1);
            if (m.y > 0 && s.y != -1 && (unsigned)g.y <= 1u)
                c1 = (unsigned)g.y * C + (unsigned)min(max(s.y, 0), C - 1);
        } else if (i0 < N) {
            int m = mask[i0], s = seg[i0], g = grp[i0];
            if (m > 0 && s != -1 && (unsigned)g <= 1u)
                c0 = (unsigned)g * C + (unsigned)min(max(s, 0), C - 1);
        }
        if (c0 < 2 * C) atomicAdd(&hist[c0], 1);
        if (c1 < 2 * C) atomicAdd(&hist[c1], 1);
        ((unsigned*)g_codes)[p] = c0 | (c1 << 16);
    }
    __syncthreads();
    for (int i = threadIdx.x; i < 2 * C; i += 256)
        g_cntpart[blockIdx.x * 2 * C + i] = hist[i];
}

// ---------------------------------------------------------------------------
// K1: column-sliced segmented sums (R2 structure: 8 warps, double-buffered
// 32-deep LDG batches, per-warp SMEM slab). Pair-collision (lo==hi) handled
// BRANCHLESSLY: vv = v + shfl_xor(v,16) computed unconditionally; SELs pick
// the merged value for half 0 and suppress half 1 -> exact & deterministic.
// ---------------------------------------------------------------------------
__global__ __launch_bounds__(256, 1)
void k1_accumulate(const float* __restrict__ pred, int N, int chTiles)
{
    extern __shared__ float sm[];
    const int tid  = threadIdx.x;
    const int wid  = tid >> 5;
    const int lane = tid & 31;
    const int half = lane >> 4;       // 0: even point of pair, 1: odd point
    const int cj   = lane & 15;       // column within slice
    float* wacc = sm + wid * WACC_F;

    for (int i = tid; i < 8 * WACC_F; i += 256) sm[i] = 0.0f;
    __syncthreads();

    const int slice   = blockIdx.x / NCHUNK;
    const int chunk   = blockIdx.x % NCHUNK;
    const int colbase = slice * COLS;
    const unsigned* codes32 = (const unsigned*)g_codes;

    auto loadtile = [&](int tt, float* v, unsigned& pk) {
        const int base = (chunk * chTiles + tt) * 64;
        pk = codes32[(base >> 1) + lane];
        if (base + 64 <= N) {
            const float* p = pred + (size_t)(base + half) * D + colbase + cj;
            #pragma unroll
            for (int u = 0; u < 32; u++) v[u] = p[(size_t)u * (2 * D)];
        } else {
            #pragma unroll
            for (int u = 0; u < 32; u++) {
                int idx = base + 2 * u + half;
                idx = idx < N ? idx : N - 1;          // clamp; code is SKIPC for OOB
                v[u] = pred[(size_t)idx * D + colbase + cj];
            }
        }
    };

    auto accum = [&](const float* v, unsigned pk) {
        #pragma unroll
        for (int u = 0; u < 32; u++) {
            const unsigned pp = __shfl_sync(0xffffffffu, pk, u);
            const float    vo = __shfl_xor_sync(0xffffffffu, v[u], 16);
            const unsigned lo = pp & 0xffffu;
            const unsigned hi = pp >> 16;
            const bool   same = (lo == hi);
            const float   val = same ? (v[u] + vo) : v[u];       // SEL
            unsigned       bc = half ? hi : lo;
            if (same && half) bc = SKIPC;                        // SEL (suppress dup)
            if (bc < 2u * C) wacc[bc * COLS + cj] += val;        // predicated RMW
        }
    };

    float va[32], vb[32];
    unsigned pka, pkb;
    int t = wid;
    if (t < chTiles) {
        loadtile(t, va, pka);
        while (true) {
            int tn = t + 8;
            if (tn < chTiles) {
                loadtile(tn, vb, pkb);
                accum(va, pka);
                int tnn = tn + 8;
                if (tnn < chTiles) {
                    loadtile(tnn, va, pka);
                    accum(vb, pkb);
                    t = tnn;
                } else { accum(vb, pkb); break; }
            } else { accum(va, pka); break; }
        }
    }
    __syncthreads();

    // reduce 8 warp slabs -> one CTA partial slab (deterministic order)
    for (int i = tid; i < WACC_F; i += 256) {
        float s = 0.0f;
        #pragma unroll
        for (int w = 0; w < 8; w++) s += sm[w * WACC_F + i];
        g_part1[(size_t)blockIdx.x * WACC_F + i] = s;
    }
}

// ---------------------------------------------------------------------------
// K2: reduce partials -> mean -> L2 normalize. grid = 2*C blocks, 128 threads.
// ---------------------------------------------------------------------------
__global__ void k2_mean_norm()
{
    __shared__ float red[D];
    const int gc = blockIdx.x;     // g*C + c
    const int d  = threadIdx.x;    // column 0..127

    float pc = 0.0f;
    for (int b = d; b < NB0; b += D) pc += (float)g_cntpart[b * 2 * C + gc];
    red[d] = pc; __syncthreads();
    for (int s = 64; s > 0; s >>= 1) { if (d < s) red[d] += red[d + s]; __syncthreads(); }
    const float cnt = fmaxf(red[0], 1.0f);
    __syncthreads();

    const int cs = d >> 4, j = d & 15;   // slice, col-in-slice (col == d)
    float s = 0.0f;
    #pragma unroll
    for (int h = 0; h < NCHUNK; h++)
        s += g_part1[(size_t)(cs * NCHUNK + h) * WACC_F + gc * COLS + j];
    const float mean = s / cnt;

    red[d] = mean * mean; __syncthreads();
    for (int s2 = 64; s2 > 0; s2 >>= 1) { if (d < s2) red[d] += red[d + s2]; __syncthreads(); }
    const float inv = rsqrtf(red[0]);

    g_ab[gc * D + d] = mean * inv;
}

// ---------------------------------------------------------------------------
// K3: block i computes logits row i AND column i in parallel groups of 256
// threads each, then both logsumexps. grid = C blocks, 512 threads.
// ---------------------------------------------------------------------------
__global__ __launch_bounds__(512)
void k3_lse()
{
    extern __shared__ float s3[];
    float* aT  = s3;                 // [D][152]
    float* bT  = aT + D * 152;       // [D][152]
    float* ai  = bT + D * 152;       // [D]
    float* bi  = ai + D;             // [D]
    float* red = bi + D;             // [2][256]
    __shared__ float diag_s, lse_s[2];

    const int i = blockIdx.x, tid = threadIdx.x;
    const int g2 = tid >> 8;         // 0: row group, 1: col group
    const int j  = tid & 255;

    for (int idx = tid; idx < C * D; idx += 512) {
        const int c = idx >> 7, d = idx & 127;
        aT[d * 152 + c] = g_ab[idx];
        bT[d * 152 + c] = g_ab[C * D + idx];
    }
    if (tid < D)            ai[tid] = g_ab[i * D + tid];
    else if (tid < 2 * D)   bi[tid - D] = g_ab[C * D + i * D + (tid - D)];
    __syncthreads();

    float x = -1e30f;
    if (j < C) {
        const float* vec = g2 ? bi : ai;
        const float* mat = g2 ? aT : bT;
        float xs = 0.0f;
        #pragma unroll 8
        for (int k = 0; k < D; k++) xs += vec[k] * mat[k * 152 + j];
        x = xs * INV_TEMP;
        if (g2 == 0 && j == i) diag_s = x;
    }

    // parallel logsumexp per group (both groups run the same barriers)
    red[tid] = x; __syncthreads();
    for (int s = 128; s > 0; s >>= 1) {
        if (j < s) red[tid] = fmaxf(red[tid], red[tid + s]);
        __syncthreads();
    }
    const float mx = red[g2 << 8]; __syncthreads();
    red[tid] = (j < C) ? expf(x - mx) : 0.0f; __syncthreads();
    for (int s = 128; s > 0; s >>= 1) {
        if (j < s) red[tid] += red[tid + s];
        __syncthreads();
    }
    if (j == 0) lse_s[g2] = mx + logf(red[g2 << 8]);
    __syncthreads();

    if (tid == 0) g_contrib[i] = lse_s[0] + lse_s[1] - 2.0f * diag_s;
}

// ---------------------------------------------------------------------------
// K4: final scalar. 1 block, 256 threads.
// ---------------------------------------------------------------------------
__global__ void k4_final(float* __restrict__ out)
{
    __shared__ float red[256];
    const int tid = threadIdx.x;
    red[tid] = (tid < C) ? g_contrib[tid] : 0.0f; __syncthreads();
    for (int s = 128; s > 0; s >>= 1) { if (tid < s) red[tid] += red[tid + s]; __syncthreads(); }
    if (tid == 0) out[0] = red[0] * (1.0f / (2.0f * C));
}

// ---------------------------------------------------------------------------
extern "C" void kernel_launch(void* const* d_in, const int* in_sizes, int n_in,
                              void* d_out, int out_size)
{
    const float* pred = (const float*)d_in[0];
    // d_in[1] = target (unused by the loss math)
    const int* mask = (const int*)d_in[2];
    const int* seg  = (const int*)d_in[3];
    const int* grp  = (const int*)d_in[4];
    const int N = in_sizes[2];

    const int totTiles = (N + 63) / 64;
    const int chTiles  = (totTiles + NCHUNK - 1) / NCHUNK;
    const int NPAD     = NCHUNK * chTiles * 64;   // <= NMAX for N <= ~2.09M

    const size_t smem1 = 8 * WACC_F * sizeof(float);               // 153.6 KB
    cudaFuncSetAttribute(k1_accumulate, cudaFuncAttributeMaxDynamicSharedMemorySize, (int)smem1);
    const size_t smem3 = (2 * D * 152 + 2 * D + 512) * sizeof(float);
    cudaFuncSetAttribute(k3_lse, cudaFuncAttributeMaxDynamicSharedMemorySize, (int)smem3);

    k0_encode<<<NB0, 256>>>(mask, seg, grp, N, NPAD);
    k1_accumulate<<<GRID1, 256, smem1>>>(pred, N, chTiles);
    k2_mean_norm<<<2 * C, D>>>();
    k3_lse<<<C, 512, smem3>>>();
    k4_final<<<1, 256>>>((float*)d_out);
}